// round 1
// baseline (speedup 1.0000x reference)
#include <cuda_runtime.h>
#include <cuda_bf16.h>
#include <cstdint>

// Problem constants (fixed by the dataset)
#define N_LEFT   100000
#define N_RIGHT  100000
#define N_EDGES  600000
#define EMB      128

// ---------------------------------------------------------------------------
// Device scratch (allocation-free rule: __device__ globals)
// ---------------------------------------------------------------------------
__device__ float g_A [N_LEFT  * EMB];   // hidden of left (then reused for right hidden)
__device__ float g_L [N_LEFT  * EMB];   // transformed left  (gather source)
__device__ float g_S [N_RIGHT * EMB];   // transformed right + scatter accumulator
__device__ float g_Ml[EMB * EMB];       // Wl2 @ Wo1[0:128]
__device__ float g_Mr[EMB * EMB];       // Wr2 @ Wo1[128:256]
__device__ float g_cl[EMB];             // bl2 @ Wo1[0:128]
__device__ float g_cr[EMB];             // br2 @ Wo1[128:256]

// ---------------------------------------------------------------------------
// Weight fusion:  M[i][j] = sum_k W2[i][k] * Wo1[off+k][j]
// grid (128, 2), block 128
// ---------------------------------------------------------------------------
__global__ void fuse_weights_kernel(const float* __restrict__ Wl2,
                                    const float* __restrict__ Wr2,
                                    const float* __restrict__ Wo1,
                                    float* __restrict__ Ml,
                                    float* __restrict__ Mr)
{
    const int i = blockIdx.x;
    const int j = threadIdx.x;
    const bool rightSide = (blockIdx.y != 0);
    const float* W2 = rightSide ? Wr2 : Wl2;
    const int off = rightSide ? EMB : 0;
    float s = 0.f;
#pragma unroll 8
    for (int k = 0; k < EMB; k++)
        s += W2[i * EMB + k] * Wo1[(off + k) * EMB + j];
    (rightSide ? Mr : Ml)[i * EMB + j] = s;
}

// c[j] = sum_k b[k] * Wo1[off+k][j];  grid(2), block 128
__global__ void fuse_bias_kernel(const float* __restrict__ bl2,
                                 const float* __restrict__ br2,
                                 const float* __restrict__ Wo1,
                                 float* __restrict__ cl,
                                 float* __restrict__ cr)
{
    const int j = threadIdx.x;
    const bool rightSide = (blockIdx.x != 0);
    const float* b = rightSide ? br2 : bl2;
    const int off = rightSide ? EMB : 0;
    float s = 0.f;
#pragma unroll 8
    for (int k = 0; k < EMB; k++)
        s += b[k] * Wo1[(off + k) * EMB + j];
    (rightSide ? cr : cl)[j] = s;
}

// ---------------------------------------------------------------------------
// SGEMM: C[M,128] = op_post( op_pre(A[M,K]) @ W[K,128] + post_bias )
//   op_pre (optional):  a -> relu(a + pre_bias[k])   (applied to A elements)
//   op_post (optional): relu
// Block tile 128x128, BK=32, 256 threads, 8x8 per-thread tile.
// Inner loop uses packed fma.rn.f32x2: k-dimension packed in pairs so each
// instruction does 2 FMAs per lane (Blackwell FFMA2 path).
// ---------------------------------------------------------------------------
#define BM 128
#define BN 128
#define BK 32

template<int K, bool PRE_RELU, bool POST_RELU>
__global__ void __launch_bounds__(256, 1)
gemm128_kernel(const float* __restrict__ A,
               const float* __restrict__ W,
               const float* __restrict__ pre_bias,   // length K (may be null if !PRE_RELU)
               const float* __restrict__ post_bias,  // length 128 or null
               float* __restrict__ C,
               int M)
{
    // k-pairs: As2[k2][m] = (A[m][2k2], A[m][2k2+1]); Ws2[k2][n] likewise.
    __shared__ float2 As2[BK / 2][BM];   // 16 KB
    __shared__ float2 Ws2[BK / 2][BN];   // 16 KB

    const int tid = threadIdx.x;
    const int tx = tid & 15;      // column group: cols tx + 16*j
    const int ty = tid >> 4;      // row group:    rows ty*8 + i
    const int row0 = blockIdx.x * BM;

    unsigned long long acc[8][8];
#pragma unroll
    for (int i = 0; i < 8; i++)
#pragma unroll
        for (int j = 0; j < 8; j++) acc[i][j] = 0ULL;

    for (int kt = 0; kt < K; kt += BK) {
        // ---- load A tile (128 x 32) transposed into k-pair layout ----
#pragma unroll
        for (int s = 0; s < 4; s++) {
            int slot = tid + s * 256;         // 0..1023
            int r  = slot >> 3;               // row within tile
            int kq = slot & 7;                // float4 index along k
            int grow = row0 + r;
            float4 v = make_float4(0.f, 0.f, 0.f, 0.f);
            if (grow < M)
                v = *(const float4*)(A + (size_t)grow * K + kt + kq * 4);
            if (PRE_RELU) {
                float4 pb = *(const float4*)(pre_bias + kt + kq * 4);
                v.x = fmaxf(v.x + pb.x, 0.f);
                v.y = fmaxf(v.y + pb.y, 0.f);
                v.z = fmaxf(v.z + pb.z, 0.f);
                v.w = fmaxf(v.w + pb.w, 0.f);
            }
            As2[kq * 2    ][r] = make_float2(v.x, v.y);
            As2[kq * 2 + 1][r] = make_float2(v.z, v.w);
        }
        // ---- load W tile (32 x 128) into k-pair layout ----
#pragma unroll
        for (int s = 0; s < 2; s++) {
            int u  = tid + s * 256;           // 0..511
            int k2 = u >> 5;                  // 0..15
            int n4 = (u & 31) * 4;            // 0..124
            const float* w0 = W + (size_t)(kt + k2 * 2) * BN + n4;
            float4 we = *(const float4*)(w0);
            float4 wo = *(const float4*)(w0 + BN);
            Ws2[k2][n4 + 0] = make_float2(we.x, wo.x);
            Ws2[k2][n4 + 1] = make_float2(we.y, wo.y);
            Ws2[k2][n4 + 2] = make_float2(we.z, wo.z);
            Ws2[k2][n4 + 3] = make_float2(we.w, wo.w);
        }
        __syncthreads();

#pragma unroll
        for (int k2 = 0; k2 < BK / 2; k2++) {
            unsigned long long a2[8], w2[8];
#pragma unroll
            for (int i = 0; i < 8; i++)
                a2[i] = *(const unsigned long long*)&As2[k2][ty * 8 + i];
#pragma unroll
            for (int j = 0; j < 8; j++)
                w2[j] = *(const unsigned long long*)&Ws2[k2][tx + j * 16];
#pragma unroll
            for (int i = 0; i < 8; i++)
#pragma unroll
                for (int j = 0; j < 8; j++)
                    asm("fma.rn.f32x2 %0, %1, %2, %0;"
                        : "+l"(acc[i][j]) : "l"(a2[i]), "l"(w2[j]));
        }
        __syncthreads();
    }

    // ---- epilogue ----
#pragma unroll
    for (int i = 0; i < 8; i++) {
        int r = row0 + ty * 8 + i;
        if (r >= M) continue;
#pragma unroll
        for (int j = 0; j < 8; j++) {
            int c = tx + j * 16;
            float2 p = *reinterpret_cast<float2*>(&acc[i][j]);
            float v = p.x + p.y;
            if (post_bias) v += post_bias[c];
            if (POST_RELU) v = fmaxf(v, 0.f);
            C[(size_t)r * BN + c] = v;
        }
    }
}

// ---------------------------------------------------------------------------
// Edge scatter: one warp per edge.
//   S[dst] += w_e * L[src]   (128 floats -> 32 lanes x float4, vector red)
// ---------------------------------------------------------------------------
__global__ void scatter_kernel(const int* __restrict__ eidx,
                               const float* __restrict__ ew,
                               const float* __restrict__ L,
                               float* __restrict__ S,
                               int E)
{
    const int warp = (blockIdx.x * blockDim.x + threadIdx.x) >> 5;
    const int lane = threadIdx.x & 31;
    if (warp >= E) return;

    const int src = eidx[warp];
    const int dst = eidx[E + warp];
    const float w = ew[warp];

    float4 v = *(const float4*)(L + (size_t)src * EMB + lane * 4);
    float* out = S + (size_t)dst * EMB + lane * 4;
    asm volatile("red.global.add.v4.f32 [%0], {%1, %2, %3, %4};"
                 :: "l"(out), "f"(w * v.x), "f"(w * v.y), "f"(w * v.z), "f"(w * v.w)
                 : "memory");
}

// ---------------------------------------------------------------------------
// Launch
// ---------------------------------------------------------------------------
extern "C" void kernel_launch(void* const* d_in, const int* in_sizes, int n_in,
                              void* d_out, int out_size)
{
    const float* left  = (const float*)d_in[0];
    const int*   eidx  = (const int*)  d_in[1];
    const float* ew    = (const float*)d_in[2];
    const float* right = (const float*)d_in[3];
    // d_in[4] = scatter_out_size (device scalar, unused: derive from out_size)
    const float* Wl1 = (const float*)d_in[5];
    const float* bl1 = (const float*)d_in[6];
    const float* Wl2 = (const float*)d_in[7];
    const float* bl2 = (const float*)d_in[8];
    const float* Wr1 = (const float*)d_in[9];
    const float* Wr2 = (const float*)d_in[10];
    const float* br2 = (const float*)d_in[11];
    const float* Wo1 = (const float*)d_in[12];
    const float* bo1 = (const float*)d_in[13];
    const float* Wo2 = (const float*)d_in[14];
    const float* bo2 = (const float*)d_in[15];

    const int nL = in_sizes[0] / 64;     // left rows   (F_LEFT = 64)
    const int E  = in_sizes[1] / 2;      // edges
    const int nR = in_sizes[3] / 64;     // right rows  (F_RIGHT = 64)
    const int nO = out_size / EMB;       // output rows (== nR)

    float *gA, *gL, *gS, *gMl, *gMr, *gcl, *gcr;
    cudaGetSymbolAddress((void**)&gA,  g_A);
    cudaGetSymbolAddress((void**)&gL,  g_L);
    cudaGetSymbolAddress((void**)&gS,  g_S);
    cudaGetSymbolAddress((void**)&gMl, g_Ml);
    cudaGetSymbolAddress((void**)&gMr, g_Mr);
    cudaGetSymbolAddress((void**)&gcl, g_cl);
    cudaGetSymbolAddress((void**)&gcr, g_cr);

    // 1) fold Wl2@Wo1a / Wr2@Wo1b (+ bias projections)
    fuse_weights_kernel<<<dim3(EMB, 2), EMB>>>(Wl2, Wr2, Wo1, gMl, gMr);
    fuse_bias_kernel<<<2, EMB>>>(bl2, br2, Wo1, gcl, gcr);

    const int gridL = (nL + BM - 1) / BM;
    const int gridR = (nR + BM - 1) / BM;
    const int gridO = (nO + BM - 1) / BM;

    // 2) A = relu(left @ Wl1 + bl1)
    gemm128_kernel<64, false, true><<<gridL, 256>>>(left, Wl1, nullptr, bl1, gA, nL);
    // 3) L = A @ Ml + cl
    gemm128_kernel<128, false, false><<<gridL, 256>>>(gA, gMl, nullptr, gcl, gL, nL);
    // 4) B = relu(right @ Wr1)          (reuses gA)
    gemm128_kernel<64, false, true><<<gridR, 256>>>(right, Wr1, nullptr, nullptr, gA, nR);
    // 5) S = B @ Mr + cr
    gemm128_kernel<128, false, false><<<gridR, 256>>>(gA, gMr, nullptr, gcr, gS, nR);
    // 6) S[dst] += e * L[src]
    scatter_kernel<<<(E + 7) / 8, 256>>>(eidx, ew, gL, gS, E);
    // 7) out = relu(S + bo1) @ Wo2 + bo2
    gemm128_kernel<128, true, false><<<gridO, 256>>>(gS, Wo2, bo1, bo2, (float*)d_out, nO);
}

// round 3
// speedup vs baseline: 1.6060x; 1.6060x over previous
#include <cuda_runtime.h>
#include <cuda_bf16.h>
#include <cstdint>

// Problem constants (fixed by the dataset)
#define N_LEFT   100000
#define N_RIGHT  100000
#define N_EDGES  600000
#define EMB      128

// ---------------------------------------------------------------------------
// Device scratch (allocation-free rule: __device__ globals)
// ---------------------------------------------------------------------------
__device__ float g_L [N_LEFT  * EMB];   // transformed left (gather source)
__device__ float g_S [N_RIGHT * EMB];   // transformed right + scatter accumulator
__device__ float g_Ml[EMB * EMB];       // Wl2 @ Wo1[0:128]
__device__ float g_Mr[EMB * EMB];       // Wr2 @ Wo1[128:256]
__device__ float g_cl[EMB];
__device__ float g_cr[EMB];

// Pre-transposed bf16 hi/lo weight images, [n][k] k-contiguous (B^T layout for
// mma row.col). 16B-aligned for uint4 traffic.
__device__ __align__(16) __nv_bfloat16 g_Wl1T[2][EMB * 64];
__device__ __align__(16) __nv_bfloat16 g_Wr1T[2][EMB * 64];
__device__ __align__(16) __nv_bfloat16 g_MlT [2][EMB * EMB];
__device__ __align__(16) __nv_bfloat16 g_MrT [2][EMB * EMB];
__device__ __align__(16) __nv_bfloat16 g_Wo2T[2][EMB * EMB];

// ---------------------------------------------------------------------------
// mma.sync m16n8k16 row.col bf16 -> f32 (baseline PTX, works on sm_100)
// ---------------------------------------------------------------------------
__device__ __forceinline__ void mma16816(float* d, const uint32_t* a, const uint32_t* b) {
    asm volatile(
        "mma.sync.aligned.m16n8k16.row.col.f32.bf16.bf16.f32 "
        "{%0,%1,%2,%3}, {%4,%5,%6,%7}, {%8,%9}, {%0,%1,%2,%3};"
        : "+f"(d[0]), "+f"(d[1]), "+f"(d[2]), "+f"(d[3])
        : "r"(a[0]), "r"(a[1]), "r"(a[2]), "r"(a[3]), "r"(b[0]), "r"(b[1]));
}

// ---------------------------------------------------------------------------
// Core MMA stage: acc[4][4][4] += split3( A[128][K] @ B[128][K]^T )
// A, B in smem as bf16 hi/lo, row stride K+8 (conflict-free fragment loads).
// Warp tiling: warp_m in {0,1} (64 rows), warp_n in {0..3} (32 cols).
// ---------------------------------------------------------------------------
template<int K>
__device__ __forceinline__ void mma_stage(const __nv_bfloat16* __restrict__ Ahi,
                                          const __nv_bfloat16* __restrict__ Alo,
                                          const __nv_bfloat16* __restrict__ Bhi,
                                          const __nv_bfloat16* __restrict__ Blo,
                                          float acc[4][4][4],
                                          int warp_m, int warp_n, int lane)
{
    constexpr int SK = K + 8;
    const int g = lane >> 2;        // 0..7
    const int c = lane & 3;         // 0..3
#pragma unroll
    for (int kc = 0; kc < K / 16; kc++) {
        const int k0 = kc * 16 + c * 2;
        uint32_t ah[4][4], al[4][4], bh[4][2], bl[4][2];
#pragma unroll
        for (int mt = 0; mt < 4; mt++) {
            const int r0 = warp_m * 64 + mt * 16 + g;
            const __nv_bfloat16* ph = Ahi + r0 * SK + k0;
            const __nv_bfloat16* pl = Alo + r0 * SK + k0;
            ah[mt][0] = *(const uint32_t*)(ph);
            ah[mt][1] = *(const uint32_t*)(ph + 8 * SK);
            ah[mt][2] = *(const uint32_t*)(ph + 8);
            ah[mt][3] = *(const uint32_t*)(ph + 8 * SK + 8);
            al[mt][0] = *(const uint32_t*)(pl);
            al[mt][1] = *(const uint32_t*)(pl + 8 * SK);
            al[mt][2] = *(const uint32_t*)(pl + 8);
            al[mt][3] = *(const uint32_t*)(pl + 8 * SK + 8);
        }
#pragma unroll
        for (int nt = 0; nt < 4; nt++) {
            const int n0 = warp_n * 32 + nt * 8 + g;
            const __nv_bfloat16* ph = Bhi + n0 * SK + k0;
            const __nv_bfloat16* pl = Blo + n0 * SK + k0;
            bh[nt][0] = *(const uint32_t*)(ph);
            bh[nt][1] = *(const uint32_t*)(ph + 8);
            bl[nt][0] = *(const uint32_t*)(pl);
            bl[nt][1] = *(const uint32_t*)(pl + 8);
        }
#pragma unroll
        for (int mt = 0; mt < 4; mt++)
#pragma unroll
            for (int nt = 0; nt < 4; nt++) {
                mma16816(acc[mt][nt], ah[mt], bh[nt]);
                mma16816(acc[mt][nt], ah[mt], bl[nt]);
                mma16816(acc[mt][nt], al[mt], bh[nt]);
            }
    }
}

// Copy a [128][K] bf16 image from gmem (packed) into padded smem (stride K+8).
template<int K>
__device__ __forceinline__ void load_B(__nv_bfloat16* __restrict__ dst,
                                       const uint4* __restrict__ src, int tid)
{
    constexpr int SK = K + 8;
    constexpr int NV = 128 * K / 8;     // uint4 count
#pragma unroll
    for (int i = tid; i < NV; i += 256) {
        const int row = i / (K / 8);
        const int col = (i % (K / 8)) * 8;
        *(uint4*)(dst + row * SK + col) = src[i];
    }
}

// Load A[row0..row0+127][0..K) fp32 from gmem, optional relu(x+pre_bias),
// split into bf16 hi/lo, store to padded smem.
template<int K, bool PRE>
__device__ __forceinline__ void load_A(__nv_bfloat16* __restrict__ hi,
                                       __nv_bfloat16* __restrict__ lo,
                                       const float* __restrict__ X,
                                       const float* __restrict__ pre_bias,
                                       int row0, int M, int tid)
{
    constexpr int SK = K + 8;
    const int row  = tid >> 1;
    const int grow = row0 + row;
    const bool valid = grow < M;
    const float* xr = X + (size_t)grow * K;
    const int cbase = (tid & 1) * (K / 2);
#pragma unroll
    for (int q = 0; q < K / 8; q++) {
        const int c0 = cbase + q * 4;
        float4 v = valid ? *(const float4*)(xr + c0) : make_float4(0.f, 0.f, 0.f, 0.f);
        if (PRE) {
            float4 pb = *(const float4*)(pre_bias + c0);
            v.x = fmaxf(v.x + pb.x, 0.f);
            v.y = fmaxf(v.y + pb.y, 0.f);
            v.z = fmaxf(v.z + pb.z, 0.f);
            v.w = fmaxf(v.w + pb.w, 0.f);
        }
        __nv_bfloat16 hx = __float2bfloat16(v.x), hy = __float2bfloat16(v.y);
        __nv_bfloat16 hz = __float2bfloat16(v.z), hw = __float2bfloat16(v.w);
        __nv_bfloat16 lx = __float2bfloat16(v.x - __bfloat162float(hx));
        __nv_bfloat16 ly = __float2bfloat16(v.y - __bfloat162float(hy));
        __nv_bfloat16 lz = __float2bfloat16(v.z - __bfloat162float(hz));
        __nv_bfloat16 lw = __float2bfloat16(v.w - __bfloat162float(hw));
        __nv_bfloat162 h0(hx, hy), h1(hz, hw), l0(lx, ly), l1(lz, lw);
        *(uint32_t*)(hi + row * SK + c0)     = *(uint32_t*)&h0;
        *(uint32_t*)(hi + row * SK + c0 + 2) = *(uint32_t*)&h1;
        *(uint32_t*)(lo + row * SK + c0)     = *(uint32_t*)&l0;
        *(uint32_t*)(lo + row * SK + c0 + 2) = *(uint32_t*)&l1;
    }
}

// ---------------------------------------------------------------------------
// Fused 2-layer MLP kernel: C = relu(X @ W1 [+ b1]) @ W2 + b2
//   X: [M][64] fp32;  W1 images: [128][64] bf16 hi/lo;  W2 images: [128][128]
// One CTA per 128 rows, 256 threads. Intermediate H kept in SMEM.
// ---------------------------------------------------------------------------
#define K1 64
#define K2 128
#define SK1 (K1 + 8)
#define SK2 (K2 + 8)
#define AB1 (128 * SK1)                 // elements per image, stage 1
#define AB2 (128 * SK2)                 // elements per image, stage 2
// smem element offsets (bf16 elements)
#define O_A1H 0
#define O_A1L (AB1)
#define O_B1H (2 * AB1)
#define O_B1L (3 * AB1)
#define O_HH  (4 * AB1)
#define O_HL  (4 * AB1 + AB2)
#define O_B2H (4 * AB1 + 2 * AB2)
#define O_B2L (4 * AB1 + 3 * AB2)
#define MLP_SMEM_BYTES ((4 * AB1 + 4 * AB2) * 2)

__global__ void __launch_bounds__(256, 1)
mlp_kernel(const float* __restrict__ X,
           const uint4* __restrict__ B1hi, const uint4* __restrict__ B1lo,
           const float* __restrict__ bias1,          // may be null
           const uint4* __restrict__ B2hi, const uint4* __restrict__ B2lo,
           const float* __restrict__ bias2,
           float* __restrict__ C, int M)
{
    extern __shared__ __nv_bfloat16 sm[];
    const int tid = threadIdx.x;
    const int wid = tid >> 5, lane = tid & 31;
    const int warp_m = wid >> 2, warp_n = wid & 3;
    const int g = lane >> 2, c = lane & 3;
    const int row0 = blockIdx.x * 128;

    load_B<K1>(sm + O_B1H, B1hi, tid);
    load_B<K1>(sm + O_B1L, B1lo, tid);
    load_B<K2>(sm + O_B2H, B2hi, tid);
    load_B<K2>(sm + O_B2L, B2lo, tid);
    load_A<K1, false>(sm + O_A1H, sm + O_A1L, X, nullptr, row0, M, tid);
    __syncthreads();

    // ---- stage 1: H = relu(X @ W1 + b1) ----
    float acc[4][4][4];
#pragma unroll
    for (int mt = 0; mt < 4; mt++)
#pragma unroll
        for (int nt = 0; nt < 4; nt++)
#pragma unroll
            for (int j = 0; j < 4; j++) acc[mt][nt][j] = 0.f;

    mma_stage<K1>(sm + O_A1H, sm + O_A1L, sm + O_B1H, sm + O_B1L,
                  acc, warp_m, warp_n, lane);

    // epilogue -> H (bf16 hi/lo) in smem
#pragma unroll
    for (int mt = 0; mt < 4; mt++) {
        const int row = warp_m * 64 + mt * 16 + g;
#pragma unroll
        for (int nt = 0; nt < 4; nt++) {
            const int col = warp_n * 32 + nt * 8 + c * 2;
            float v0 = acc[mt][nt][0], v1 = acc[mt][nt][1];
            float v2 = acc[mt][nt][2], v3 = acc[mt][nt][3];
            if (bias1) {
                float2 b = *(const float2*)(bias1 + col);
                v0 += b.x; v1 += b.y; v2 += b.x; v3 += b.y;
            }
            v0 = fmaxf(v0, 0.f); v1 = fmaxf(v1, 0.f);
            v2 = fmaxf(v2, 0.f); v3 = fmaxf(v3, 0.f);
            __nv_bfloat16 h0 = __float2bfloat16(v0), h1 = __float2bfloat16(v1);
            __nv_bfloat16 h2 = __float2bfloat16(v2), h3 = __float2bfloat16(v3);
            __nv_bfloat162 hp0(h0, h1), hp1(h2, h3);
            __nv_bfloat162 lp0(__float2bfloat16(v0 - __bfloat162float(h0)),
                               __float2bfloat16(v1 - __bfloat162float(h1)));
            __nv_bfloat162 lp1(__float2bfloat16(v2 - __bfloat162float(h2)),
                               __float2bfloat16(v3 - __bfloat162float(h3)));
            *(uint32_t*)(sm + O_HH + row * SK2 + col)       = *(uint32_t*)&hp0;
            *(uint32_t*)(sm + O_HH + (row + 8) * SK2 + col) = *(uint32_t*)&hp1;
            *(uint32_t*)(sm + O_HL + row * SK2 + col)       = *(uint32_t*)&lp0;
            *(uint32_t*)(sm + O_HL + (row + 8) * SK2 + col) = *(uint32_t*)&lp1;
        }
    }
    __syncthreads();

    // ---- stage 2: C = H @ W2 + b2 ----
#pragma unroll
    for (int mt = 0; mt < 4; mt++)
#pragma unroll
        for (int nt = 0; nt < 4; nt++)
#pragma unroll
            for (int j = 0; j < 4; j++) acc[mt][nt][j] = 0.f;

    mma_stage<K2>(sm + O_HH, sm + O_HL, sm + O_B2H, sm + O_B2L,
                  acc, warp_m, warp_n, lane);

#pragma unroll
    for (int mt = 0; mt < 4; mt++) {
        const int r = row0 + warp_m * 64 + mt * 16 + g;
#pragma unroll
        for (int nt = 0; nt < 4; nt++) {
            const int col = warp_n * 32 + nt * 8 + c * 2;
            float2 b = *(const float2*)(bias2 + col);
            if (r < M) {
                float2 o0 = make_float2(acc[mt][nt][0] + b.x, acc[mt][nt][1] + b.y);
                *(float2*)(C + (size_t)r * EMB + col) = o0;
            }
            if (r + 8 < M) {
                float2 o1 = make_float2(acc[mt][nt][2] + b.x, acc[mt][nt][3] + b.y);
                *(float2*)(C + (size_t)(r + 8) * EMB + col) = o1;
            }
        }
    }
}

// ---------------------------------------------------------------------------
// Output GEMM: out = relu(S + bo1) @ Wo2 + bo2   (K = 128)
// ---------------------------------------------------------------------------
#define OG_AH 0
#define OG_AL (AB2)
#define OG_BH (2 * AB2)
#define OG_BL (3 * AB2)
#define OG_SMEM_BYTES (4 * AB2 * 2)

__global__ void __launch_bounds__(256, 1)
out_gemm_kernel(const float* __restrict__ S,
                const uint4* __restrict__ Bhi, const uint4* __restrict__ Blo,
                const float* __restrict__ pre_bias,
                const float* __restrict__ post_bias,
                float* __restrict__ C, int M)
{
    extern __shared__ __nv_bfloat16 sm[];
    const int tid = threadIdx.x;
    const int wid = tid >> 5, lane = tid & 31;
    const int warp_m = wid >> 2, warp_n = wid & 3;
    const int g = lane >> 2, c = lane & 3;
    const int row0 = blockIdx.x * 128;

    load_B<K2>(sm + OG_BH, Bhi, tid);
    load_B<K2>(sm + OG_BL, Blo, tid);
    load_A<K2, true>(sm + OG_AH, sm + OG_AL, S, pre_bias, row0, M, tid);
    __syncthreads();

    float acc[4][4][4];
#pragma unroll
    for (int mt = 0; mt < 4; mt++)
#pragma unroll
        for (int nt = 0; nt < 4; nt++)
#pragma unroll
            for (int j = 0; j < 4; j++) acc[mt][nt][j] = 0.f;

    mma_stage<K2>(sm + OG_AH, sm + OG_AL, sm + OG_BH, sm + OG_BL,
                  acc, warp_m, warp_n, lane);

#pragma unroll
    for (int mt = 0; mt < 4; mt++) {
        const int r = row0 + warp_m * 64 + mt * 16 + g;
#pragma unroll
        for (int nt = 0; nt < 4; nt++) {
            const int col = warp_n * 32 + nt * 8 + c * 2;
            float2 b = *(const float2*)(post_bias + col);
            if (r < M) {
                float2 o0 = make_float2(acc[mt][nt][0] + b.x, acc[mt][nt][1] + b.y);
                *(float2*)(C + (size_t)r * EMB + col) = o0;
            }
            if (r + 8 < M) {
                float2 o1 = make_float2(acc[mt][nt][2] + b.x, acc[mt][nt][3] + b.y);
                *(float2*)(C + (size_t)(r + 8) * EMB + col) = o1;
            }
        }
    }
}

// ---------------------------------------------------------------------------
// Weight fusion:  M[i][j] = sum_k W2[i][k] * Wo1[off+k][j];  grid(128,2) block 128
// ---------------------------------------------------------------------------
__global__ void fuse_weights_kernel(const float* __restrict__ Wl2,
                                    const float* __restrict__ Wr2,
                                    const float* __restrict__ Wo1,
                                    float* __restrict__ Ml,
                                    float* __restrict__ Mr)
{
    const int i = blockIdx.x, j = threadIdx.x;
    const bool rs = (blockIdx.y != 0);
    const float* W2 = rs ? Wr2 : Wl2;
    const int off = rs ? EMB : 0;
    float s = 0.f;
#pragma unroll 8
    for (int k = 0; k < EMB; k++)
        s += W2[i * EMB + k] * Wo1[(off + k) * EMB + j];
    (rs ? Mr : Ml)[i * EMB + j] = s;
}

__global__ void fuse_bias_kernel(const float* __restrict__ bl2,
                                 const float* __restrict__ br2,
                                 const float* __restrict__ Wo1,
                                 float* __restrict__ cl,
                                 float* __restrict__ cr)
{
    const int j = threadIdx.x;
    const bool rs = (blockIdx.x != 0);
    const float* b = rs ? br2 : bl2;
    const int off = rs ? EMB : 0;
    float s = 0.f;
#pragma unroll 8
    for (int k = 0; k < EMB; k++)
        s += b[k] * Wo1[(off + k) * EMB + j];
    (rs ? cr : cl)[j] = s;
}

// ---------------------------------------------------------------------------
// Prep: W [K x 128] fp32 -> transposed bf16 hi/lo images [128][K] (k-contig).
// grid 5, block 128.
// ---------------------------------------------------------------------------
__global__ void prep_weights_kernel(const float* __restrict__ Wl1,
                                    const float* __restrict__ Wr1,
                                    const float* __restrict__ Ml,
                                    const float* __restrict__ Mr,
                                    const float* __restrict__ Wo2,
                                    __nv_bfloat16* __restrict__ Wl1T,
                                    __nv_bfloat16* __restrict__ Wr1T,
                                    __nv_bfloat16* __restrict__ MlT,
                                    __nv_bfloat16* __restrict__ MrT,
                                    __nv_bfloat16* __restrict__ Wo2T)
{
    const int n = threadIdx.x;
    const float* W; __nv_bfloat16* T; int K;
    switch (blockIdx.x) {
        case 0: W = Wl1; T = Wl1T; K = 64;  break;
        case 1: W = Wr1; T = Wr1T; K = 64;  break;
        case 2: W = Ml;  T = MlT;  K = 128; break;
        case 3: W = Mr;  T = MrT;  K = 128; break;
        default: W = Wo2; T = Wo2T; K = 128; break;
    }
    __nv_bfloat16* Hi = T;
    __nv_bfloat16* Lo = T + EMB * K;   // second image follows first
    for (int k = 0; k < K; k++) {
        float w = W[k * EMB + n];
        __nv_bfloat16 h = __float2bfloat16(w);
        __nv_bfloat16 l = __float2bfloat16(w - __bfloat162float(h));
        Hi[n * K + k] = h;
        Lo[n * K + k] = l;
    }
}

// ---------------------------------------------------------------------------
// Edge scatter: one warp per edge.  S[dst] += w_e * L[src]
// ---------------------------------------------------------------------------
__global__ void scatter_kernel(const int* __restrict__ eidx,
                               const float* __restrict__ ew,
                               const float* __restrict__ L,
                               float* __restrict__ S,
                               int E)
{
    const int warp = (blockIdx.x * blockDim.x + threadIdx.x) >> 5;
    const int lane = threadIdx.x & 31;
    if (warp >= E) return;

    const int src = eidx[warp];
    const int dst = eidx[E + warp];
    const float w = ew[warp];

    float4 v = *(const float4*)(L + (size_t)src * EMB + lane * 4);
    float* out = S + (size_t)dst * EMB + lane * 4;
    asm volatile("red.global.add.v4.f32 [%0], {%1, %2, %3, %4};"
                 :: "l"(out), "f"(w * v.x), "f"(w * v.y), "f"(w * v.z), "f"(w * v.w)
                 : "memory");
}

// ---------------------------------------------------------------------------
// Launch
// ---------------------------------------------------------------------------
extern "C" void kernel_launch(void* const* d_in, const int* in_sizes, int n_in,
                              void* d_out, int out_size)
{
    const float* left  = (const float*)d_in[0];
    const int*   eidx  = (const int*)  d_in[1];
    const float* ew    = (const float*)d_in[2];
    const float* right = (const float*)d_in[3];
    const float* Wl1 = (const float*)d_in[5];
    const float* bl1 = (const float*)d_in[6];
    const float* Wl2 = (const float*)d_in[7];
    const float* bl2 = (const float*)d_in[8];
    const float* Wr1 = (const float*)d_in[9];
    const float* Wr2 = (const float*)d_in[10];
    const float* br2 = (const float*)d_in[11];
    const float* Wo1 = (const float*)d_in[12];
    const float* bo1 = (const float*)d_in[13];
    const float* Wo2 = (const float*)d_in[14];
    const float* bo2 = (const float*)d_in[15];

    const int nL = in_sizes[0] / 64;
    const int E  = in_sizes[1] / 2;
    const int nR = in_sizes[3] / 64;
    const int nO = out_size / EMB;

    float *gL, *gS, *gMl, *gMr, *gcl, *gcr;
    cudaGetSymbolAddress((void**)&gL,  g_L);
    cudaGetSymbolAddress((void**)&gS,  g_S);
    cudaGetSymbolAddress((void**)&gMl, g_Ml);
    cudaGetSymbolAddress((void**)&gMr, g_Mr);
    cudaGetSymbolAddress((void**)&gcl, g_cl);
    cudaGetSymbolAddress((void**)&gcr, g_cr);

    __nv_bfloat16 *wl1t, *wr1t, *mlt, *mrt, *wo2t;
    cudaGetSymbolAddress((void**)&wl1t, g_Wl1T);
    cudaGetSymbolAddress((void**)&wr1t, g_Wr1T);
    cudaGetSymbolAddress((void**)&mlt,  g_MlT);
    cudaGetSymbolAddress((void**)&mrt,  g_MrT);
    cudaGetSymbolAddress((void**)&wo2t, g_Wo2T);

    cudaFuncSetAttribute(mlp_kernel,      cudaFuncAttributeMaxDynamicSharedMemorySize, MLP_SMEM_BYTES);
    cudaFuncSetAttribute(out_gemm_kernel, cudaFuncAttributeMaxDynamicSharedMemorySize, OG_SMEM_BYTES);

    // 1) fold Wl2@Wo1a / Wr2@Wo1b (+ bias projections), then transpose+split
    fuse_weights_kernel<<<dim3(EMB, 2), EMB>>>(Wl2, Wr2, Wo1, gMl, gMr);
    fuse_bias_kernel<<<2, EMB>>>(bl2, br2, Wo1, gcl, gcr);
    prep_weights_kernel<<<5, EMB>>>(Wl1, Wr1, gMl, gMr, Wo2, wl1t, wr1t, mlt, mrt, wo2t);

    const int gridL = (nL + 127) / 128;
    const int gridR = (nR + 127) / 128;
    const int gridO = (nO + 127) / 128;

    // hi/lo image pointers (lo follows hi)
    const uint4* wl1h = (const uint4*)wl1t;
    const uint4* wl1l = (const uint4*)(wl1t + EMB * 64);
    const uint4* wr1h = (const uint4*)wr1t;
    const uint4* wr1l = (const uint4*)(wr1t + EMB * 64);
    const uint4* mlh  = (const uint4*)mlt;
    const uint4* mll  = (const uint4*)(mlt + EMB * EMB);
    const uint4* mrh  = (const uint4*)mrt;
    const uint4* mrl  = (const uint4*)(mrt + EMB * EMB);
    const uint4* wo2h = (const uint4*)wo2t;
    const uint4* wo2l = (const uint4*)(wo2t + EMB * EMB);

    // 2) L = relu(left@Wl1 + bl1) @ Ml + cl
    mlp_kernel<<<gridL, 256, MLP_SMEM_BYTES>>>(left, wl1h, wl1l, bl1, mlh, mll, gcl, gL, nL);
    // 3) S = relu(right@Wr1) @ Mr + cr
    mlp_kernel<<<gridR, 256, MLP_SMEM_BYTES>>>(right, wr1h, wr1l, nullptr, mrh, mrl, gcr, gS, nR);
    // 4) S[dst] += e * L[src]
    scatter_kernel<<<(E + 7) / 8, 256>>>(eidx, ew, gL, gS, E);
    // 5) out = relu(S + bo1) @ Wo2 + bo2
    out_gemm_kernel<<<gridO, 256, OG_SMEM_BYTES>>>(gS, wo2h, wo2l, bo1, bo2, (float*)d_out, nO);
}

// round 5
// speedup vs baseline: 1.6655x; 1.0370x over previous
#include <cuda_runtime.h>
#include <cuda_bf16.h>
#include <cstdint>

// Problem constants (fixed by the dataset)
#define N_LEFT   100000
#define N_RIGHT  100000
#define N_EDGES  600000
#define EMB      128

// ---------------------------------------------------------------------------
// Device scratch (allocation-free rule: __device__ globals)
// ---------------------------------------------------------------------------
__device__ float g_L [N_LEFT  * EMB];   // transformed left (gather source)
__device__ float g_S [N_RIGHT * EMB];   // transformed right + conv accumulator
__device__ float g_Ml[EMB * EMB];       // Wl2 @ Wo1[0:128]
__device__ float g_Mr[EMB * EMB];       // Wr2 @ Wo1[128:256]
__device__ float g_cl[EMB];
__device__ float g_cr[EMB];

// CSR scratch
__device__ int   g_cnt [N_RIGHT];       // counts, then cursors
__device__ int   g_rowptr[N_RIGHT + 1];
__device__ int   g_excl[N_RIGHT];
__device__ int   g_part[1024];
__device__ int   g_partoff[1024];
__device__ int   g_esrc[N_EDGES];
__device__ float g_ewp [N_EDGES];

// Pre-transposed bf16 hi/lo weight images, [n][k] k-contiguous (B^T layout).
__device__ __align__(16) __nv_bfloat16 g_Wl1T[2][EMB * 64];
__device__ __align__(16) __nv_bfloat16 g_Wr1T[2][EMB * 64];
__device__ __align__(16) __nv_bfloat16 g_MlT [2][EMB * EMB];
__device__ __align__(16) __nv_bfloat16 g_MrT [2][EMB * EMB];
__device__ __align__(16) __nv_bfloat16 g_Wo2T[2][EMB * EMB];

// ---------------------------------------------------------------------------
// mma.sync m16n8k16 row.col bf16 -> f32 (baseline PTX)
// ---------------------------------------------------------------------------
__device__ __forceinline__ void mma16816(float* d, const uint32_t* a, const uint32_t* b) {
    asm volatile(
        "mma.sync.aligned.m16n8k16.row.col.f32.bf16.bf16.f32 "
        "{%0,%1,%2,%3}, {%4,%5,%6,%7}, {%8,%9}, {%0,%1,%2,%3};"
        : "+f"(d[0]), "+f"(d[1]), "+f"(d[2]), "+f"(d[3])
        : "r"(a[0]), "r"(a[1]), "r"(a[2]), "r"(a[3]), "r"(b[0]), "r"(b[1]));
}
__device__ __forceinline__ void ldsm_x4(uint32_t& r0, uint32_t& r1, uint32_t& r2, uint32_t& r3,
                                        uint32_t addr) {
    asm volatile("ldmatrix.sync.aligned.m8n8.x4.shared.b16 {%0,%1,%2,%3}, [%4];"
                 : "=r"(r0), "=r"(r1), "=r"(r2), "=r"(r3) : "r"(addr));
}
__device__ __forceinline__ uint32_t cvta_s(const void* p) {
    return (uint32_t)__cvta_generic_to_shared(p);
}

// ---------------------------------------------------------------------------
// Core MMA stage with ldmatrix: acc += split3( A[128][K] @ B[128][K]^T )
// smem row stride K+8 elems (144B / 272B — conflict-free 16B-row ldmatrix).
// Warp tiling: warp_m in {0,1} (64 rows), warp_n in {0..3} (32 cols).
// ---------------------------------------------------------------------------
template<int K>
__device__ __forceinline__ void mma_stage(const __nv_bfloat16* __restrict__ Ahi,
                                          const __nv_bfloat16* __restrict__ Alo,
                                          const __nv_bfloat16* __restrict__ Bhi,
                                          const __nv_bfloat16* __restrict__ Blo,
                                          float acc[4][4][4],
                                          int warp_m, int warp_n, int lane)
{
    constexpr int SK = K + 8;
    const int tr = lane & 7, quad = lane >> 3;
    // A fragment source: lanes 0-7 rows+0/k0, 8-15 rows+8/k0, 16-23 rows+0/k8, 24-31 rows+8/k8
    const int a_row = warp_m * 64 + tr + (quad & 1) * 8;
    const int a_col = (quad >> 1) * 8;
    // B fragment pair: lanes 0-7 n+0/k0, 8-15 n+0/k8, 16-23 n+8/k0, 24-31 n+8/k8
    const int b_row = warp_n * 32 + tr + (quad >> 1) * 8;
    const int b_col = (quad & 1) * 8;

    uint32_t aAh = cvta_s(Ahi) + (uint32_t)(a_row * SK + a_col) * 2;
    uint32_t aAl = cvta_s(Alo) + (uint32_t)(a_row * SK + a_col) * 2;
    uint32_t aBh = cvta_s(Bhi) + (uint32_t)(b_row * SK + b_col) * 2;
    uint32_t aBl = cvta_s(Blo) + (uint32_t)(b_row * SK + b_col) * 2;

#pragma unroll
    for (int kc = 0; kc < K / 16; kc++) {
        const uint32_t ko = kc * 32;   // 16 elems = 32 bytes
        uint32_t ah[4][4], al[4][4], bh[2][4], bl[2][4];
#pragma unroll
        for (int mt = 0; mt < 4; mt++) {
            const uint32_t mo = (uint32_t)(mt * 16 * SK) * 2 + ko;
            ldsm_x4(ah[mt][0], ah[mt][1], ah[mt][2], ah[mt][3], aAh + mo);
            ldsm_x4(al[mt][0], al[mt][1], al[mt][2], al[mt][3], aAl + mo);
        }
#pragma unroll
        for (int np = 0; np < 2; np++) {
            const uint32_t no = (uint32_t)(np * 16 * SK) * 2 + ko;
            ldsm_x4(bh[np][0], bh[np][1], bh[np][2], bh[np][3], aBh + no);
            ldsm_x4(bl[np][0], bl[np][1], bl[np][2], bl[np][3], aBl + no);
        }
#pragma unroll
        for (int mt = 0; mt < 4; mt++)
#pragma unroll
            for (int nt = 0; nt < 4; nt++) {
                const uint32_t* ph = &bh[nt >> 1][(nt & 1) * 2];
                const uint32_t* pl = &bl[nt >> 1][(nt & 1) * 2];
                mma16816(acc[mt][nt], ah[mt], ph);
                mma16816(acc[mt][nt], ah[mt], pl);
                mma16816(acc[mt][nt], al[mt], ph);
            }
    }
}

// Copy a [128][K] bf16 image from gmem (packed) into padded smem (stride K+8).
template<int K>
__device__ __forceinline__ void load_B(__nv_bfloat16* __restrict__ dst,
                                       const uint4* __restrict__ src, int tid)
{
    constexpr int SK = K + 8;
    constexpr int NV = 128 * K / 8;
#pragma unroll
    for (int i = tid; i < NV; i += 256) {
        const int row = i / (K / 8);
        const int col = (i % (K / 8)) * 8;
        *(uint4*)(dst + row * SK + col) = src[i];
    }
}

// Load A[row0..+127][0..K) fp32, optional relu(x+pre_bias), bf16 hi/lo split.
template<int K, bool PRE>
__device__ __forceinline__ void load_A(__nv_bfloat16* __restrict__ hi,
                                       __nv_bfloat16* __restrict__ lo,
                                       const float* __restrict__ X,
                                       const float* __restrict__ pre_bias,
                                       int row0, int M, int tid)
{
    constexpr int SK = K + 8;
    const int row  = tid >> 1;
    const int grow = row0 + row;
    const bool valid = grow < M;
    const float* xr = X + (size_t)grow * K;
    const int cbase = (tid & 1) * (K / 2);
#pragma unroll
    for (int q = 0; q < K / 8; q++) {
        const int c0 = cbase + q * 4;
        float4 v = valid ? *(const float4*)(xr + c0) : make_float4(0.f, 0.f, 0.f, 0.f);
        if (PRE) {
            float4 pb = *(const float4*)(pre_bias + c0);
            v.x = fmaxf(v.x + pb.x, 0.f);
            v.y = fmaxf(v.y + pb.y, 0.f);
            v.z = fmaxf(v.z + pb.z, 0.f);
            v.w = fmaxf(v.w + pb.w, 0.f);
        }
        __nv_bfloat16 hx = __float2bfloat16(v.x), hy = __float2bfloat16(v.y);
        __nv_bfloat16 hz = __float2bfloat16(v.z), hw = __float2bfloat16(v.w);
        __nv_bfloat16 lx = __float2bfloat16(v.x - __bfloat162float(hx));
        __nv_bfloat16 ly = __float2bfloat16(v.y - __bfloat162float(hy));
        __nv_bfloat16 lz = __float2bfloat16(v.z - __bfloat162float(hz));
        __nv_bfloat16 lw = __float2bfloat16(v.w - __bfloat162float(hw));
        __nv_bfloat162 h0(hx, hy), h1(hz, hw), l0(lx, ly), l1(lz, lw);
        *(uint32_t*)(hi + row * SK + c0)     = *(uint32_t*)&h0;
        *(uint32_t*)(hi + row * SK + c0 + 2) = *(uint32_t*)&h1;
        *(uint32_t*)(lo + row * SK + c0)     = *(uint32_t*)&l0;
        *(uint32_t*)(lo + row * SK + c0 + 2) = *(uint32_t*)&l1;
    }
}

// ---------------------------------------------------------------------------
// Fused 2-layer MLP: C = relu(X @ W1 [+ b1]) @ W2 + b2
// ---------------------------------------------------------------------------
#define K1 64
#define K2 128
#define SK1 (K1 + 8)
#define SK2 (K2 + 8)
#define AB1 (128 * SK1)
#define AB2 (128 * SK2)
#define O_A1H 0
#define O_A1L (AB1)
#define O_B1H (2 * AB1)
#define O_B1L (3 * AB1)
#define O_HH  (4 * AB1)
#define O_HL  (4 * AB1 + AB2)
#define O_B2H (4 * AB1 + 2 * AB2)
#define O_B2L (4 * AB1 + 3 * AB2)
#define MLP_SMEM_BYTES ((4 * AB1 + 4 * AB2) * 2)

__global__ void __launch_bounds__(256, 1)
mlp_kernel(const float* __restrict__ X,
           const uint4* __restrict__ B1hi, const uint4* __restrict__ B1lo,
           const float* __restrict__ bias1,
           const uint4* __restrict__ B2hi, const uint4* __restrict__ B2lo,
           const float* __restrict__ bias2,
           float* __restrict__ C, int M)
{
    extern __shared__ __nv_bfloat16 sm[];
    const int tid = threadIdx.x;
    const int wid = tid >> 5, lane = tid & 31;
    const int warp_m = wid >> 2, warp_n = wid & 3;
    const int g = lane >> 2, c = lane & 3;
    const int row0 = blockIdx.x * 128;

    load_B<K1>(sm + O_B1H, B1hi, tid);
    load_B<K1>(sm + O_B1L, B1lo, tid);
    load_B<K2>(sm + O_B2H, B2hi, tid);
    load_B<K2>(sm + O_B2L, B2lo, tid);
    load_A<K1, false>(sm + O_A1H, sm + O_A1L, X, nullptr, row0, M, tid);
    __syncthreads();

    float acc[4][4][4];
#pragma unroll
    for (int mt = 0; mt < 4; mt++)
#pragma unroll
        for (int nt = 0; nt < 4; nt++)
#pragma unroll
            for (int j = 0; j < 4; j++) acc[mt][nt][j] = 0.f;

    mma_stage<K1>(sm + O_A1H, sm + O_A1L, sm + O_B1H, sm + O_B1L,
                  acc, warp_m, warp_n, lane);

    // epilogue -> H (bf16 hi/lo) in smem
#pragma unroll
    for (int mt = 0; mt < 4; mt++) {
        const int row = warp_m * 64 + mt * 16 + g;
#pragma unroll
        for (int nt = 0; nt < 4; nt++) {
            const int col = warp_n * 32 + nt * 8 + c * 2;
            float v0 = acc[mt][nt][0], v1 = acc[mt][nt][1];
            float v2 = acc[mt][nt][2], v3 = acc[mt][nt][3];
            if (bias1) {
                float2 b = *(const float2*)(bias1 + col);
                v0 += b.x; v1 += b.y; v2 += b.x; v3 += b.y;
            }
            v0 = fmaxf(v0, 0.f); v1 = fmaxf(v1, 0.f);
            v2 = fmaxf(v2, 0.f); v3 = fmaxf(v3, 0.f);
            __nv_bfloat16 h0 = __float2bfloat16(v0), h1 = __float2bfloat16(v1);
            __nv_bfloat16 h2 = __float2bfloat16(v2), h3 = __float2bfloat16(v3);
            __nv_bfloat162 hp0(h0, h1), hp1(h2, h3);
            __nv_bfloat162 lp0(__float2bfloat16(v0 - __bfloat162float(h0)),
                               __float2bfloat16(v1 - __bfloat162float(h1)));
            __nv_bfloat162 lp1(__float2bfloat16(v2 - __bfloat162float(h2)),
                               __float2bfloat16(v3 - __bfloat162float(h3)));
            *(uint32_t*)(sm + O_HH + row * SK2 + col)       = *(uint32_t*)&hp0;
            *(uint32_t*)(sm + O_HH + (row + 8) * SK2 + col) = *(uint32_t*)&hp1;
            *(uint32_t*)(sm + O_HL + row * SK2 + col)       = *(uint32_t*)&lp0;
            *(uint32_t*)(sm + O_HL + (row + 8) * SK2 + col) = *(uint32_t*)&lp1;
        }
    }
    __syncthreads();

#pragma unroll
    for (int mt = 0; mt < 4; mt++)
#pragma unroll
        for (int nt = 0; nt < 4; nt++)
#pragma unroll
            for (int j = 0; j < 4; j++) acc[mt][nt][j] = 0.f;

    mma_stage<K2>(sm + O_HH, sm + O_HL, sm + O_B2H, sm + O_B2L,
                  acc, warp_m, warp_n, lane);

#pragma unroll
    for (int mt = 0; mt < 4; mt++) {
        const int r = row0 + warp_m * 64 + mt * 16 + g;
#pragma unroll
        for (int nt = 0; nt < 4; nt++) {
            const int col = warp_n * 32 + nt * 8 + c * 2;
            float2 b = *(const float2*)(bias2 + col);
            if (r < M) {
                float2 o0 = make_float2(acc[mt][nt][0] + b.x, acc[mt][nt][1] + b.y);
                *(float2*)(C + (size_t)r * EMB + col) = o0;
            }
            if (r + 8 < M) {
                float2 o1 = make_float2(acc[mt][nt][2] + b.x, acc[mt][nt][3] + b.y);
                *(float2*)(C + (size_t)(r + 8) * EMB + col) = o1;
            }
        }
    }
}

// ---------------------------------------------------------------------------
// Output GEMM: out = relu(S + bo1) @ Wo2 + bo2
// ---------------------------------------------------------------------------
#define OG_AH 0
#define OG_AL (AB2)
#define OG_BH (2 * AB2)
#define OG_BL (3 * AB2)
#define OG_SMEM_BYTES (4 * AB2 * 2)

__global__ void __launch_bounds__(256, 1)
out_gemm_kernel(const float* __restrict__ S,
                const uint4* __restrict__ Bhi, const uint4* __restrict__ Blo,
                const float* __restrict__ pre_bias,
                const float* __restrict__ post_bias,
                float* __restrict__ C, int M)
{
    extern __shared__ __nv_bfloat16 sm[];
    const int tid = threadIdx.x;
    const int wid = tid >> 5, lane = tid & 31;
    const int warp_m = wid >> 2, warp_n = wid & 3;
    const int g = lane >> 2, c = lane & 3;
    const int row0 = blockIdx.x * 128;

    load_B<K2>(sm + OG_BH, Bhi, tid);
    load_B<K2>(sm + OG_BL, Blo, tid);
    load_A<K2, true>(sm + OG_AH, sm + OG_AL, S, pre_bias, row0, M, tid);
    __syncthreads();

    float acc[4][4][4];
#pragma unroll
    for (int mt = 0; mt < 4; mt++)
#pragma unroll
        for (int nt = 0; nt < 4; nt++)
#pragma unroll
            for (int j = 0; j < 4; j++) acc[mt][nt][j] = 0.f;

    mma_stage<K2>(sm + OG_AH, sm + OG_AL, sm + OG_BH, sm + OG_BL,
                  acc, warp_m, warp_n, lane);

#pragma unroll
    for (int mt = 0; mt < 4; mt++) {
        const int r = row0 + warp_m * 64 + mt * 16 + g;
#pragma unroll
        for (int nt = 0; nt < 4; nt++) {
            const int col = warp_n * 32 + nt * 8 + c * 2;
            float2 b = *(const float2*)(post_bias + col);
            if (r < M) {
                float2 o0 = make_float2(acc[mt][nt][0] + b.x, acc[mt][nt][1] + b.y);
                *(float2*)(C + (size_t)r * EMB + col) = o0;
            }
            if (r + 8 < M) {
                float2 o1 = make_float2(acc[mt][nt][2] + b.x, acc[mt][nt][3] + b.y);
                *(float2*)(C + (size_t)(r + 8) * EMB + col) = o1;
            }
        }
    }
}

// ---------------------------------------------------------------------------
// Weight fusion + prep
// ---------------------------------------------------------------------------
__global__ void fuse_weights_kernel(const float* __restrict__ Wl2,
                                    const float* __restrict__ Wr2,
                                    const float* __restrict__ Wo1,
                                    float* __restrict__ Ml,
                                    float* __restrict__ Mr)
{
    const int i = blockIdx.x, j = threadIdx.x;
    const bool rs = (blockIdx.y != 0);
    const float* W2 = rs ? Wr2 : Wl2;
    const int off = rs ? EMB : 0;
    float s = 0.f;
#pragma unroll 8
    for (int k = 0; k < EMB; k++)
        s += W2[i * EMB + k] * Wo1[(off + k) * EMB + j];
    (rs ? Mr : Ml)[i * EMB + j] = s;
}

__global__ void fuse_bias_kernel(const float* __restrict__ bl2,
                                 const float* __restrict__ br2,
                                 const float* __restrict__ Wo1,
                                 float* __restrict__ cl,
                                 float* __restrict__ cr)
{
    const int j = threadIdx.x;
    const bool rs = (blockIdx.x != 0);
    const float* b = rs ? br2 : bl2;
    const int off = rs ? EMB : 0;
    float s = 0.f;
#pragma unroll 8
    for (int k = 0; k < EMB; k++)
        s += b[k] * Wo1[(off + k) * EMB + j];
    (rs ? cr : cl)[j] = s;
}

__global__ void prep_weights_kernel(const float* __restrict__ Wl1,
                                    const float* __restrict__ Wr1,
                                    const float* __restrict__ Ml,
                                    const float* __restrict__ Mr,
                                    const float* __restrict__ Wo2,
                                    __nv_bfloat16* __restrict__ Wl1T,
                                    __nv_bfloat16* __restrict__ Wr1T,
                                    __nv_bfloat16* __restrict__ MlT,
                                    __nv_bfloat16* __restrict__ MrT,
                                    __nv_bfloat16* __restrict__ Wo2T)
{
    const int n = threadIdx.x;
    const float* W; __nv_bfloat16* T; int K;
    switch (blockIdx.x) {
        case 0: W = Wl1; T = Wl1T; K = 64;  break;
        case 1: W = Wr1; T = Wr1T; K = 64;  break;
        case 2: W = Ml;  T = MlT;  K = 128; break;
        case 3: W = Mr;  T = MrT;  K = 128; break;
        default: W = Wo2; T = Wo2T; K = 128; break;
    }
    __nv_bfloat16* Hi = T;
    __nv_bfloat16* Lo = T + EMB * K;
    for (int k = 0; k < K; k++) {
        float w = W[k * EMB + n];
        __nv_bfloat16 h = __float2bfloat16(w);
        __nv_bfloat16 l = __float2bfloat16(w - __bfloat162float(h));
        Hi[n * K + k] = h;
        Lo[n * K + k] = l;
    }
}

// ---------------------------------------------------------------------------
// CSR build: histogram -> block-scan -> offsets -> fill
// ---------------------------------------------------------------------------
__global__ void hist_kernel(const int* __restrict__ eidx, int* __restrict__ cnt, int E) {
    const int e = blockIdx.x * blockDim.x + threadIdx.x;
    if (e < E) atomicAdd(&cnt[eidx[E + e]], 1);
}

__global__ void scan_block_kernel(const int* __restrict__ cnt, int* __restrict__ excl,
                                  int* __restrict__ part, int n) {
    __shared__ int sh[512];
    const int tid = threadIdx.x;
    const int i = blockIdx.x * 512 + tid;
    int v = (i < n) ? cnt[i] : 0;
    int x = v;
    sh[tid] = x;
    __syncthreads();
#pragma unroll
    for (int d = 1; d < 512; d <<= 1) {
        int t = (tid >= d) ? sh[tid - d] : 0;
        __syncthreads();
        x += t;
        sh[tid] = x;
        __syncthreads();
    }
    if (i < n) excl[i] = x - v;
    if (tid == 511) part[blockIdx.x] = x;
}

__global__ void scan_part_kernel(int* __restrict__ part, int* __restrict__ partoff, int nb) {
    __shared__ int sh[1024];
    const int tid = threadIdx.x;
    int v = (tid < nb) ? part[tid] : 0;
    int x = v;
    sh[tid] = x;
    __syncthreads();
#pragma unroll
    for (int d = 1; d < 1024; d <<= 1) {
        int t = (tid >= d) ? sh[tid - d] : 0;
        __syncthreads();
        x += t;
        sh[tid] = x;
        __syncthreads();
    }
    if (tid < nb) partoff[tid] = x - v;
}

__global__ void finalize_rowptr_kernel(const int* __restrict__ excl,
                                       const int* __restrict__ partoff,
                                       int* __restrict__ rowptr,
                                       int* __restrict__ cursor,
                                       int n, int E) {
    const int i = blockIdx.x * 512 + threadIdx.x;
    if (i < n) {
        int r = excl[i] + partoff[blockIdx.x];
        rowptr[i] = r;
        cursor[i] = r;
    }
    if (i == 0) rowptr[n] = E;
}

__global__ void fill_kernel(const int* __restrict__ eidx, const float* __restrict__ ew,
                            int* __restrict__ cursor,
                            int* __restrict__ esrc, float* __restrict__ ewp, int E) {
    const int e = blockIdx.x * blockDim.x + threadIdx.x;
    if (e >= E) return;
    const int src = eidx[e];
    const int dst = eidx[E + e];
    const int pos = atomicAdd(&cursor[dst], 1);
    esrc[pos] = src;
    ewp[pos] = ew[e];
}

// ---------------------------------------------------------------------------
// Gather: warp per dst row.  S[r] += sum_j w_j * L[src_j]   (no atomics)
// ---------------------------------------------------------------------------
__global__ void gather_kernel(const int* __restrict__ rowptr,
                              const int* __restrict__ esrc,
                              const float* __restrict__ ewp,
                              const float* __restrict__ L,
                              float* __restrict__ S, int n)
{
    const int r = (blockIdx.x * blockDim.x + threadIdx.x) >> 5;
    const int lane = threadIdx.x & 31;
    if (r >= n) return;
    const int beg = rowptr[r], end = rowptr[r + 1];
    if (beg == end) return;

    float4 acc = *(const float4*)(S + (size_t)r * EMB + lane * 4);
    int j = beg;
    for (; j + 1 < end; j += 2) {
        const int s0 = esrc[j],     s1 = esrc[j + 1];
        const float w0 = ewp[j],    w1 = ewp[j + 1];
        float4 v0 = *(const float4*)(L + (size_t)s0 * EMB + lane * 4);
        float4 v1 = *(const float4*)(L + (size_t)s1 * EMB + lane * 4);
        acc.x += w0 * v0.x + w1 * v1.x;
        acc.y += w0 * v0.y + w1 * v1.y;
        acc.z += w0 * v0.z + w1 * v1.z;
        acc.w += w0 * v0.w + w1 * v1.w;
    }
    if (j < end) {
        const int s0 = esrc[j];
        const float w0 = ewp[j];
        float4 v0 = *(const float4*)(L + (size_t)s0 * EMB + lane * 4);
        acc.x += w0 * v0.x; acc.y += w0 * v0.y;
        acc.z += w0 * v0.z; acc.w += w0 * v0.w;
    }
    *(float4*)(S + (size_t)r * EMB + lane * 4) = acc;
}

// ---------------------------------------------------------------------------
// Launch
// ---------------------------------------------------------------------------
extern "C" void kernel_launch(void* const* d_in, const int* in_sizes, int n_in,
                              void* d_out, int out_size)
{
    const float* left  = (const float*)d_in[0];
    const int*   eidx  = (const int*)  d_in[1];
    const float* ew    = (const float*)d_in[2];
    const float* right = (const float*)d_in[3];
    const float* Wl1 = (const float*)d_in[5];
    const float* bl1 = (const float*)d_in[6];
    const float* Wl2 = (const float*)d_in[7];
    const float* bl2 = (const float*)d_in[8];
    const float* Wr1 = (const float*)d_in[9];
    const float* Wr2 = (const float*)d_in[10];
    const float* br2 = (const float*)d_in[11];
    const float* Wo1 = (const float*)d_in[12];
    const float* bo1 = (const float*)d_in[13];
    const float* Wo2 = (const float*)d_in[14];
    const float* bo2 = (const float*)d_in[15];

    const int nL = in_sizes[0] / 64;
    const int E  = in_sizes[1] / 2;
    const int nR = in_sizes[3] / 64;
    const int nO = out_size / EMB;

    float *gL, *gS, *gMl, *gMr, *gcl, *gcr;
    cudaGetSymbolAddress((void**)&gL,  g_L);
    cudaGetSymbolAddress((void**)&gS,  g_S);
    cudaGetSymbolAddress((void**)&gMl, g_Ml);
    cudaGetSymbolAddress((void**)&gMr, g_Mr);
    cudaGetSymbolAddress((void**)&gcl, g_cl);
    cudaGetSymbolAddress((void**)&gcr, g_cr);

    int *gCnt, *gRow, *gExcl, *gPart, *gPoff, *gEsrc;
    float* gEwp;
    cudaGetSymbolAddress((void**)&gCnt,  g_cnt);
    cudaGetSymbolAddress((void**)&gRow,  g_rowptr);
    cudaGetSymbolAddress((void**)&gExcl, g_excl);
    cudaGetSymbolAddress((void**)&gPart, g_part);
    cudaGetSymbolAddress((void**)&gPoff, g_partoff);
    cudaGetSymbolAddress((void**)&gEsrc, g_esrc);
    cudaGetSymbolAddress((void**)&gEwp,  g_ewp);

    __nv_bfloat16 *wl1t, *wr1t, *mlt, *mrt, *wo2t;
    cudaGetSymbolAddress((void**)&wl1t, g_Wl1T);
    cudaGetSymbolAddress((void**)&wr1t, g_Wr1T);
    cudaGetSymbolAddress((void**)&mlt,  g_MlT);
    cudaGetSymbolAddress((void**)&mrt,  g_MrT);
    cudaGetSymbolAddress((void**)&wo2t, g_Wo2T);

    cudaFuncSetAttribute(mlp_kernel,      cudaFuncAttributeMaxDynamicSharedMemorySize, MLP_SMEM_BYTES);
    cudaFuncSetAttribute(out_gemm_kernel, cudaFuncAttributeMaxDynamicSharedMemorySize, OG_SMEM_BYTES);

    // ---- weight prep ----
    fuse_weights_kernel<<<dim3(EMB, 2), EMB>>>(Wl2, Wr2, Wo1, gMl, gMr);
    fuse_bias_kernel<<<2, EMB>>>(bl2, br2, Wo1, gcl, gcr);
    prep_weights_kernel<<<5, EMB>>>(Wl1, Wr1, gMl, gMr, Wo2, wl1t, wr1t, mlt, mrt, wo2t);

    // ---- CSR build ----
    cudaMemsetAsync(gCnt, 0, (size_t)nR * sizeof(int));
    hist_kernel<<<(E + 255) / 256, 256>>>(eidx, gCnt, E);
    const int NB = (nR + 511) / 512;
    scan_block_kernel<<<NB, 512>>>(gCnt, gExcl, gPart, nR);
    scan_part_kernel<<<1, 1024>>>(gPart, gPoff, NB);
    finalize_rowptr_kernel<<<NB, 512>>>(gExcl, gPoff, gRow, gCnt, nR, E);
    fill_kernel<<<(E + 255) / 256, 256>>>(eidx, ew, gCnt, gEsrc, gEwp, E);

    const int gridL = (nL + 127) / 128;
    const int gridR = (nR + 127) / 128;
    const int gridO = (nO + 127) / 128;

    const uint4* wl1h = (const uint4*)wl1t;
    const uint4* wl1l = (const uint4*)(wl1t + EMB * 64);
    const uint4* wr1h = (const uint4*)wr1t;
    const uint4* wr1l = (const uint4*)(wr1t + EMB * 64);
    const uint4* mlh  = (const uint4*)mlt;
    const uint4* mll  = (const uint4*)(mlt + EMB * EMB);
    const uint4* mrh  = (const uint4*)mrt;
    const uint4* mrl  = (const uint4*)(mrt + EMB * EMB);
    const uint4* wo2h = (const uint4*)wo2t;
    const uint4* wo2l = (const uint4*)(wo2t + EMB * EMB);

    // L = relu(left@Wl1 + bl1) @ Ml + cl
    mlp_kernel<<<gridL, 256, MLP_SMEM_BYTES>>>(left, wl1h, wl1l, bl1, mlh, mll, gcl, gL, nL);
    // S = relu(right@Wr1) @ Mr + cr
    mlp_kernel<<<gridR, 256, MLP_SMEM_BYTES>>>(right, wr1h, wr1l, nullptr, mrh, mrl, gcr, gS, nR);
    // S[r] += sum_j w_j * L[src_j]
    gather_kernel<<<(nR * 32 + 255) / 256, 256>>>(gRow, gEsrc, gEwp, gL, gS, nR);
    // out = relu(S + bo1) @ Wo2 + bo2
    out_gemm_kernel<<<gridO, 256, OG_SMEM_BYTES>>>(gS, wo2h, wo2l, bo1, bo2, (float*)d_out, nO);
}

// round 6
// speedup vs baseline: 1.7075x; 1.0252x over previous
#include <cuda_runtime.h>
#include <cuda_bf16.h>
#include <cstdint>

// Problem constants (fixed by the dataset)
#define N_LEFT   100000
#define N_RIGHT  100000
#define N_EDGES  600000
#define EMB      128

// ---------------------------------------------------------------------------
// Device scratch (allocation-free rule: __device__ globals)
// ---------------------------------------------------------------------------
__device__ float g_L [N_LEFT  * EMB];   // transformed left (gather source)
__device__ float g_S [N_RIGHT * EMB];   // transformed right
__device__ float g_Ml[EMB * EMB];       // Wl2 @ Wo1[0:128]
__device__ float g_Mr[EMB * EMB];       // Wr2 @ Wo1[128:256]
__device__ float g_cl[EMB];
__device__ float g_cr[EMB];

// CSR scratch
__device__ int   g_cnt [N_RIGHT];       // counts, then cursors
__device__ int   g_rowptr[N_RIGHT + 1];
__device__ int   g_excl[N_RIGHT];
__device__ int   g_part[1024];
__device__ int   g_partoff[1024];
__device__ int2  g_epack[N_EDGES];      // (src, bitcast(weight))

// Pre-transposed bf16 hi/lo weight images, [n][k] k-contiguous (B^T layout).
__device__ __align__(16) __nv_bfloat16 g_Wl1T[2][EMB * 64];
__device__ __align__(16) __nv_bfloat16 g_Wr1T[2][EMB * 64];
__device__ __align__(16) __nv_bfloat16 g_MlT [2][EMB * EMB];
__device__ __align__(16) __nv_bfloat16 g_MrT [2][EMB * EMB];
__device__ __align__(16) __nv_bfloat16 g_Wo2T[2][EMB * EMB];

// ---------------------------------------------------------------------------
// mma.sync m16n8k16 row.col bf16 -> f32 ;  ldmatrix
// ---------------------------------------------------------------------------
__device__ __forceinline__ void mma16816(float* d, const uint32_t* a, const uint32_t* b) {
    asm volatile(
        "mma.sync.aligned.m16n8k16.row.col.f32.bf16.bf16.f32 "
        "{%0,%1,%2,%3}, {%4,%5,%6,%7}, {%8,%9}, {%0,%1,%2,%3};"
        : "+f"(d[0]), "+f"(d[1]), "+f"(d[2]), "+f"(d[3])
        : "r"(a[0]), "r"(a[1]), "r"(a[2]), "r"(a[3]), "r"(b[0]), "r"(b[1]));
}
__device__ __forceinline__ void ldsm_x4(uint32_t& r0, uint32_t& r1, uint32_t& r2, uint32_t& r3,
                                        uint32_t addr) {
    asm volatile("ldmatrix.sync.aligned.m8n8.x4.shared.b16 {%0,%1,%2,%3}, [%4];"
                 : "=r"(r0), "=r"(r1), "=r"(r2), "=r"(r3) : "r"(addr));
}
__device__ __forceinline__ uint32_t cvta_s(const void* p) {
    return (uint32_t)__cvta_generic_to_shared(p);
}

// ---------------------------------------------------------------------------
// MMA stage: acc[MT][4][4] += split3( A[MT*32][K] @ B[128][K]^T )
// smem row stride K+8 (16B-aligned rows, conflict-free ldmatrix).
// warp_m in {0,1} covers MT*16-row slabs; warp_n in {0..3} covers 32 cols.
// ---------------------------------------------------------------------------
template<int K, int MT>
__device__ __forceinline__ void mma_stage(const __nv_bfloat16* __restrict__ Ahi,
                                          const __nv_bfloat16* __restrict__ Alo,
                                          const __nv_bfloat16* __restrict__ Bhi,
                                          const __nv_bfloat16* __restrict__ Blo,
                                          float acc[][4][4],
                                          int warp_m, int warp_n, int lane)
{
    constexpr int SK = K + 8;
    const int tr = lane & 7, quad = lane >> 3;
    const int a_row = warp_m * (MT * 16) + tr + (quad & 1) * 8;
    const int a_col = (quad >> 1) * 8;
    const int b_row = warp_n * 32 + tr + (quad >> 1) * 8;
    const int b_col = (quad & 1) * 8;

    uint32_t aAh = cvta_s(Ahi) + (uint32_t)(a_row * SK + a_col) * 2;
    uint32_t aAl = cvta_s(Alo) + (uint32_t)(a_row * SK + a_col) * 2;
    uint32_t aBh = cvta_s(Bhi) + (uint32_t)(b_row * SK + b_col) * 2;
    uint32_t aBl = cvta_s(Blo) + (uint32_t)(b_row * SK + b_col) * 2;

#pragma unroll
    for (int kc = 0; kc < K / 16; kc++) {
        const uint32_t ko = kc * 32;   // 16 elems = 32 bytes
        uint32_t ah[MT][4], al[MT][4], bh[2][4], bl[2][4];
#pragma unroll
        for (int mt = 0; mt < MT; mt++) {
            const uint32_t mo = (uint32_t)(mt * 16 * SK) * 2 + ko;
            ldsm_x4(ah[mt][0], ah[mt][1], ah[mt][2], ah[mt][3], aAh + mo);
            ldsm_x4(al[mt][0], al[mt][1], al[mt][2], al[mt][3], aAl + mo);
        }
#pragma unroll
        for (int np = 0; np < 2; np++) {
            const uint32_t no = (uint32_t)(np * 16 * SK) * 2 + ko;
            ldsm_x4(bh[np][0], bh[np][1], bh[np][2], bh[np][3], aBh + no);
            ldsm_x4(bl[np][0], bl[np][1], bl[np][2], bl[np][3], aBl + no);
        }
#pragma unroll
        for (int mt = 0; mt < MT; mt++)
#pragma unroll
            for (int nt = 0; nt < 4; nt++) {
                const uint32_t* ph = &bh[nt >> 1][(nt & 1) * 2];
                const uint32_t* pl = &bl[nt >> 1][(nt & 1) * 2];
                mma16816(acc[mt][nt], ah[mt], ph);
                mma16816(acc[mt][nt], ah[mt], pl);
                mma16816(acc[mt][nt], al[mt], ph);
            }
    }
}

// Copy a [128][K] bf16 image from gmem (packed) into padded smem (stride K+8).
template<int K>
__device__ __forceinline__ void load_B(__nv_bfloat16* __restrict__ dst,
                                       const uint4* __restrict__ src, int tid)
{
    constexpr int SK = K + 8;
    constexpr int NV = 128 * K / 8;
#pragma unroll
    for (int i = tid; i < NV; i += 256) {
        const int row = i / (K / 8);
        const int col = (i % (K / 8)) * 8;
        *(uint4*)(dst + row * SK + col) = src[i];
    }
}

// Load A[row0..+63][0..K) fp32 from gmem, bf16 hi/lo split, padded smem.
// 256 threads, 64 rows -> 4 threads/row, K/4 cols each.
template<int K>
__device__ __forceinline__ void load_A64(__nv_bfloat16* __restrict__ hi,
                                         __nv_bfloat16* __restrict__ lo,
                                         const float* __restrict__ X,
                                         int row0, int M, int tid)
{
    constexpr int SK = K + 8;
    const int row  = tid >> 2;
    const int grow = row0 + row;
    const bool valid = grow < M;
    const float* xr = X + (size_t)grow * K;
    const int cbase = (tid & 3) * (K / 4);
#pragma unroll
    for (int q = 0; q < K / 16; q++) {
        const int c0 = cbase + q * 4;
        float4 v = valid ? *(const float4*)(xr + c0) : make_float4(0.f, 0.f, 0.f, 0.f);
        __nv_bfloat16 hx = __float2bfloat16(v.x), hy = __float2bfloat16(v.y);
        __nv_bfloat16 hz = __float2bfloat16(v.z), hw = __float2bfloat16(v.w);
        __nv_bfloat16 lx = __float2bfloat16(v.x - __bfloat162float(hx));
        __nv_bfloat16 ly = __float2bfloat16(v.y - __bfloat162float(hy));
        __nv_bfloat16 lz = __float2bfloat16(v.z - __bfloat162float(hz));
        __nv_bfloat16 lw = __float2bfloat16(v.w - __bfloat162float(hw));
        __nv_bfloat162 h0(hx, hy), h1(hz, hw), l0(lx, ly), l1(lz, lw);
        *(uint32_t*)(hi + row * SK + c0)     = *(uint32_t*)&h0;
        *(uint32_t*)(hi + row * SK + c0 + 2) = *(uint32_t*)&h1;
        *(uint32_t*)(lo + row * SK + c0)     = *(uint32_t*)&l0;
        *(uint32_t*)(lo + row * SK + c0 + 2) = *(uint32_t*)&l1;
    }
}

// ---------------------------------------------------------------------------
// Fused 2-layer MLP, M=64 per CTA, overlaid smem (2 CTAs/SM):
//   C = relu(X @ W1 [+ b1]) @ W2 + b2
// smem element layout (bf16):
//   [B1: 0..18432)                 -> overlaid by H in stage 2
//   [A1: 18432..27648) [X: 27648..53248) -> overlaid by B2 in stage 2
// ---------------------------------------------------------------------------
#define K1 64
#define K2 128
#define SK1 (K1 + 8)
#define SK2 (K2 + 8)
#define M_B1H 0
#define M_B1L (128 * SK1)                   // 9216
#define M_A1H (2 * 128 * SK1)               // 18432
#define M_A1L (M_A1H + 64 * SK1)            // 23040
#define M_HH  0
#define M_HL  (64 * SK2)                    // 8704
#define M_B2H 18432
#define M_B2L (M_B2H + 128 * SK2)           // 35840
#define MLP_SMEM_ELEMS (M_B2L + 128 * SK2)  // 53248
#define MLP_SMEM_BYTES (MLP_SMEM_ELEMS * 2) // 106496

__global__ void __launch_bounds__(256, 2)
mlp_kernel(const float* __restrict__ X,
           const uint4* __restrict__ B1hi, const uint4* __restrict__ B1lo,
           const float* __restrict__ bias1,
           const uint4* __restrict__ B2hi, const uint4* __restrict__ B2lo,
           const float* __restrict__ bias2,
           float* __restrict__ C, int M)
{
    extern __shared__ __nv_bfloat16 sm[];
    const int tid = threadIdx.x;
    const int wid = tid >> 5, lane = tid & 31;
    const int warp_m = wid >> 2, warp_n = wid & 3;
    const int g = lane >> 2, c = lane & 3;
    const int row0 = blockIdx.x * 64;

    load_B<K1>(sm + M_B1H, B1hi, tid);
    load_B<K1>(sm + M_B1L, B1lo, tid);
    load_A64<K1>(sm + M_A1H, sm + M_A1L, X, row0, M, tid);
    __syncthreads();

    float acc[2][4][4];
#pragma unroll
    for (int mt = 0; mt < 2; mt++)
#pragma unroll
        for (int nt = 0; nt < 4; nt++)
#pragma unroll
            for (int j = 0; j < 4; j++) acc[mt][nt][j] = 0.f;

    mma_stage<K1, 2>(sm + M_A1H, sm + M_A1L, sm + M_B1H, sm + M_B1L,
                     acc, warp_m, warp_n, lane);
    __syncthreads();   // all warps done reading A1/B1

    // epilogue 1: H = relu(acc + b1) -> bf16 hi/lo over B1 region
#pragma unroll
    for (int mt = 0; mt < 2; mt++) {
        const int row = warp_m * 32 + mt * 16 + g;
#pragma unroll
        for (int nt = 0; nt < 4; nt++) {
            const int col = warp_n * 32 + nt * 8 + c * 2;
            float v0 = acc[mt][nt][0], v1 = acc[mt][nt][1];
            float v2 = acc[mt][nt][2], v3 = acc[mt][nt][3];
            if (bias1) {
                float2 b = *(const float2*)(bias1 + col);
                v0 += b.x; v1 += b.y; v2 += b.x; v3 += b.y;
            }
            v0 = fmaxf(v0, 0.f); v1 = fmaxf(v1, 0.f);
            v2 = fmaxf(v2, 0.f); v3 = fmaxf(v3, 0.f);
            __nv_bfloat16 h0 = __float2bfloat16(v0), h1 = __float2bfloat16(v1);
            __nv_bfloat16 h2 = __float2bfloat16(v2), h3 = __float2bfloat16(v3);
            __nv_bfloat162 hp0(h0, h1), hp1(h2, h3);
            __nv_bfloat162 lp0(__float2bfloat16(v0 - __bfloat162float(h0)),
                               __float2bfloat16(v1 - __bfloat162float(h1)));
            __nv_bfloat162 lp1(__float2bfloat16(v2 - __bfloat162float(h2)),
                               __float2bfloat16(v3 - __bfloat162float(h3)));
            *(uint32_t*)(sm + M_HH + row * SK2 + col)       = *(uint32_t*)&hp0;
            *(uint32_t*)(sm + M_HH + (row + 8) * SK2 + col) = *(uint32_t*)&hp1;
            *(uint32_t*)(sm + M_HL + row * SK2 + col)       = *(uint32_t*)&lp0;
            *(uint32_t*)(sm + M_HL + (row + 8) * SK2 + col) = *(uint32_t*)&lp1;
        }
    }
    // load B2 over A1/X region (A1 fully consumed)
    load_B<K2>(sm + M_B2H, B2hi, tid);
    load_B<K2>(sm + M_B2L, B2lo, tid);
    __syncthreads();

#pragma unroll
    for (int mt = 0; mt < 2; mt++)
#pragma unroll
        for (int nt = 0; nt < 4; nt++)
#pragma unroll
            for (int j = 0; j < 4; j++) acc[mt][nt][j] = 0.f;

    mma_stage<K2, 2>(sm + M_HH, sm + M_HL, sm + M_B2H, sm + M_B2L,
                     acc, warp_m, warp_n, lane);

#pragma unroll
    for (int mt = 0; mt < 2; mt++) {
        const int r = row0 + warp_m * 32 + mt * 16 + g;
#pragma unroll
        for (int nt = 0; nt < 4; nt++) {
            const int col = warp_n * 32 + nt * 8 + c * 2;
            float2 b = *(const float2*)(bias2 + col);
            if (r < M) {
                float2 o0 = make_float2(acc[mt][nt][0] + b.x, acc[mt][nt][1] + b.y);
                *(float2*)(C + (size_t)r * EMB + col) = o0;
            }
            if (r + 8 < M) {
                float2 o1 = make_float2(acc[mt][nt][2] + b.x, acc[mt][nt][3] + b.y);
                *(float2*)(C + (size_t)(r + 8) * EMB + col) = o1;
            }
        }
    }
}

// ---------------------------------------------------------------------------
// Fused gather + output GEMM, M=64 per CTA (2 CTAs/SM):
//   conv_r = S[r] + sum_j w_j * L[src_j]
//   out    = relu(conv + bo1) @ Wo2 + bo2
// ---------------------------------------------------------------------------
#define F_AH 0
#define F_AL (64 * SK2)                  // 8704
#define F_BH (2 * 64 * SK2)              // 17408
#define F_BL (F_BH + 128 * SK2)          // 34816
#define F_SMEM_ELEMS (F_BL + 128 * SK2)  // 52224
#define F_SMEM_BYTES (F_SMEM_ELEMS * 2)  // 104448

__global__ void __launch_bounds__(256, 2)
out_fused_kernel(const float* __restrict__ S,
                 const int* __restrict__ rowptr,
                 const int2* __restrict__ epack,
                 const float* __restrict__ L,
                 const uint4* __restrict__ Bhi, const uint4* __restrict__ Blo,
                 const float* __restrict__ bo1,
                 const float* __restrict__ bo2,
                 float* __restrict__ C, int M)
{
    extern __shared__ __nv_bfloat16 sm[];
    const int tid = threadIdx.x;
    const int wid = tid >> 5, lane = tid & 31;
    const int warp_m = wid >> 2, warp_n = wid & 3;
    const int g = lane >> 2, c = lane & 3;
    const int row0 = blockIdx.x * 64;

    load_B<K2>(sm + F_BH, Bhi, tid);
    load_B<K2>(sm + F_BL, Blo, tid);

    const float4 pb = *(const float4*)(bo1 + lane * 4);

    // gather: each warp handles 8 rows
#pragma unroll 1
    for (int rl = wid * 8; rl < wid * 8 + 8; rl++) {
        const int r = row0 + rl;
        float4 acc = make_float4(0.f, 0.f, 0.f, 0.f);
        if (r < M) {
            acc = *(const float4*)(S + (size_t)r * EMB + lane * 4);
            const int beg = rowptr[r], end = rowptr[r + 1];
            int j = beg;
            for (; j + 4 <= end; j += 4) {
                const int2 e0 = epack[j],     e1 = epack[j + 1];
                const int2 e2 = epack[j + 2], e3 = epack[j + 3];
                const float4 v0 = *(const float4*)(L + (size_t)e0.x * EMB + lane * 4);
                const float4 v1 = *(const float4*)(L + (size_t)e1.x * EMB + lane * 4);
                const float4 v2 = *(const float4*)(L + (size_t)e2.x * EMB + lane * 4);
                const float4 v3 = *(const float4*)(L + (size_t)e3.x * EMB + lane * 4);
                const float w0 = __int_as_float(e0.y), w1 = __int_as_float(e1.y);
                const float w2 = __int_as_float(e2.y), w3 = __int_as_float(e3.y);
                acc.x += w0 * v0.x + w1 * v1.x + w2 * v2.x + w3 * v3.x;
                acc.y += w0 * v0.y + w1 * v1.y + w2 * v2.y + w3 * v3.y;
                acc.z += w0 * v0.z + w1 * v1.z + w2 * v2.z + w3 * v3.z;
                acc.w += w0 * v0.w + w1 * v1.w + w2 * v2.w + w3 * v3.w;
            }
            for (; j < end; j++) {
                const int2 e0 = epack[j];
                const float w0 = __int_as_float(e0.y);
                const float4 v0 = *(const float4*)(L + (size_t)e0.x * EMB + lane * 4);
                acc.x += w0 * v0.x; acc.y += w0 * v0.y;
                acc.z += w0 * v0.z; acc.w += w0 * v0.w;
            }
            acc.x = fmaxf(acc.x + pb.x, 0.f);
            acc.y = fmaxf(acc.y + pb.y, 0.f);
            acc.z = fmaxf(acc.z + pb.z, 0.f);
            acc.w = fmaxf(acc.w + pb.w, 0.f);
        }
        // split + store into smem A image: row rl, cols lane*4..lane*4+3
        __nv_bfloat16 hx = __float2bfloat16(acc.x), hy = __float2bfloat16(acc.y);
        __nv_bfloat16 hz = __float2bfloat16(acc.z), hw = __float2bfloat16(acc.w);
        __nv_bfloat162 h0(hx, hy), h1(hz, hw);
        __nv_bfloat162 l0(__float2bfloat16(acc.x - __bfloat162float(hx)),
                          __float2bfloat16(acc.y - __bfloat162float(hy)));
        __nv_bfloat162 l1(__float2bfloat16(acc.z - __bfloat162float(hz)),
                          __float2bfloat16(acc.w - __bfloat162float(hw)));
        const int c0 = lane * 4;
        *(uint32_t*)(sm + F_AH + rl * SK2 + c0)     = *(uint32_t*)&h0;
        *(uint32_t*)(sm + F_AH + rl * SK2 + c0 + 2) = *(uint32_t*)&h1;
        *(uint32_t*)(sm + F_AL + rl * SK2 + c0)     = *(uint32_t*)&l0;
        *(uint32_t*)(sm + F_AL + rl * SK2 + c0 + 2) = *(uint32_t*)&l1;
    }
    __syncthreads();

    float acc[2][4][4];
#pragma unroll
    for (int mt = 0; mt < 2; mt++)
#pragma unroll
        for (int nt = 0; nt < 4; nt++)
#pragma unroll
            for (int j = 0; j < 4; j++) acc[mt][nt][j] = 0.f;

    mma_stage<K2, 2>(sm + F_AH, sm + F_AL, sm + F_BH, sm + F_BL,
                     acc, warp_m, warp_n, lane);

#pragma unroll
    for (int mt = 0; mt < 2; mt++) {
        const int r = row0 + warp_m * 32 + mt * 16 + g;
#pragma unroll
        for (int nt = 0; nt < 4; nt++) {
            const int col = warp_n * 32 + nt * 8 + c * 2;
            float2 b = *(const float2*)(bo2 + col);
            if (r < M) {
                float2 o0 = make_float2(acc[mt][nt][0] + b.x, acc[mt][nt][1] + b.y);
                *(float2*)(C + (size_t)r * EMB + col) = o0;
            }
            if (r + 8 < M) {
                float2 o1 = make_float2(acc[mt][nt][2] + b.x, acc[mt][nt][3] + b.y);
                *(float2*)(C + (size_t)(r + 8) * EMB + col) = o1;
            }
        }
    }
}

// ---------------------------------------------------------------------------
// Weight fusion + prep
// ---------------------------------------------------------------------------
__global__ void fuse_weights_kernel(const float* __restrict__ Wl2,
                                    const float* __restrict__ Wr2,
                                    const float* __restrict__ Wo1,
                                    float* __restrict__ Ml,
                                    float* __restrict__ Mr)
{
    const int i = blockIdx.x, j = threadIdx.x;
    const bool rs = (blockIdx.y != 0);
    const float* W2 = rs ? Wr2 : Wl2;
    const int off = rs ? EMB : 0;
    float s = 0.f;
#pragma unroll 8
    for (int k = 0; k < EMB; k++)
        s += W2[i * EMB + k] * Wo1[(off + k) * EMB + j];
    (rs ? Mr : Ml)[i * EMB + j] = s;
}

__global__ void fuse_bias_kernel(const float* __restrict__ bl2,
                                 const float* __restrict__ br2,
                                 const float* __restrict__ Wo1,
                                 float* __restrict__ cl,
                                 float* __restrict__ cr)
{
    const int j = threadIdx.x;
    const bool rs = (blockIdx.x != 0);
    const float* b = rs ? br2 : bl2;
    const int off = rs ? EMB : 0;
    float s = 0.f;
#pragma unroll 8
    for (int k = 0; k < EMB; k++)
        s += b[k] * Wo1[(off + k) * EMB + j];
    (rs ? cr : cl)[j] = s;
}

__global__ void prep_weights_kernel(const float* __restrict__ Wl1,
                                    const float* __restrict__ Wr1,
                                    const float* __restrict__ Ml,
                                    const float* __restrict__ Mr,
                                    const float* __restrict__ Wo2,
                                    __nv_bfloat16* __restrict__ Wl1T,
                                    __nv_bfloat16* __restrict__ Wr1T,
                                    __nv_bfloat16* __restrict__ MlT,
                                    __nv_bfloat16* __restrict__ MrT,
                                    __nv_bfloat16* __restrict__ Wo2T)
{
    const int n = threadIdx.x;
    const float* W; __nv_bfloat16* T; int K;
    switch (blockIdx.x) {
        case 0: W = Wl1; T = Wl1T; K = 64;  break;
        case 1: W = Wr1; T = Wr1T; K = 64;  break;
        case 2: W = Ml;  T = MlT;  K = 128; break;
        case 3: W = Mr;  T = MrT;  K = 128; break;
        default: W = Wo2; T = Wo2T; K = 128; break;
    }
    __nv_bfloat16* Hi = T;
    __nv_bfloat16* Lo = T + EMB * K;
    for (int k = 0; k < K; k++) {
        float w = W[k * EMB + n];
        __nv_bfloat16 h = __float2bfloat16(w);
        __nv_bfloat16 l = __float2bfloat16(w - __bfloat162float(h));
        Hi[n * K + k] = h;
        Lo[n * K + k] = l;
    }
}

// ---------------------------------------------------------------------------
// CSR build: histogram -> block-scan -> offsets -> fill (packed payload)
// ---------------------------------------------------------------------------
__global__ void hist_kernel(const int* __restrict__ eidx, int* __restrict__ cnt, int E) {
    const int e = blockIdx.x * blockDim.x + threadIdx.x;
    if (e < E) atomicAdd(&cnt[eidx[E + e]], 1);
}

__global__ void scan_block_kernel(const int* __restrict__ cnt, int* __restrict__ excl,
                                  int* __restrict__ part, int n) {
    __shared__ int sh[512];
    const int tid = threadIdx.x;
    const int i = blockIdx.x * 512 + tid;
    int v = (i < n) ? cnt[i] : 0;
    int x = v;
    sh[tid] = x;
    __syncthreads();
#pragma unroll
    for (int d = 1; d < 512; d <<= 1) {
        int t = (tid >= d) ? sh[tid - d] : 0;
        __syncthreads();
        x += t;
        sh[tid] = x;
        __syncthreads();
    }
    if (i < n) excl[i] = x - v;
    if (tid == 511) part[blockIdx.x] = x;
}

__global__ void scan_part_kernel(int* __restrict__ part, int* __restrict__ partoff, int nb) {
    __shared__ int sh[1024];
    const int tid = threadIdx.x;
    int v = (tid < nb) ? part[tid] : 0;
    int x = v;
    sh[tid] = x;
    __syncthreads();
#pragma unroll
    for (int d = 1; d < 1024; d <<= 1) {
        int t = (tid >= d) ? sh[tid - d] : 0;
        __syncthreads();
        x += t;
        sh[tid] = x;
        __syncthreads();
    }
    if (tid < nb) partoff[tid] = x - v;
}

__global__ void finalize_rowptr_kernel(const int* __restrict__ excl,
                                       const int* __restrict__ partoff,
                                       int* __restrict__ rowptr,
                                       int* __restrict__ cursor,
                                       int n, int E) {
    const int i = blockIdx.x * 512 + threadIdx.x;
    if (i < n) {
        int r = excl[i] + partoff[blockIdx.x];
        rowptr[i] = r;
        cursor[i] = r;
    }
    if (i == 0) rowptr[n] = E;
}

__global__ void fill_kernel(const int* __restrict__ eidx, const float* __restrict__ ew,
                            int* __restrict__ cursor,
                            int2* __restrict__ epack, int E) {
    const int e = blockIdx.x * blockDim.x + threadIdx.x;
    if (e >= E) return;
    const int src = eidx[e];
    const int dst = eidx[E + e];
    const int pos = atomicAdd(&cursor[dst], 1);
    epack[pos] = make_int2(src, __float_as_int(ew[e]));
}

// ---------------------------------------------------------------------------
// Launch
// ---------------------------------------------------------------------------
extern "C" void kernel_launch(void* const* d_in, const int* in_sizes, int n_in,
                              void* d_out, int out_size)
{
    const float* left  = (const float*)d_in[0];
    const int*   eidx  = (const int*)  d_in[1];
    const float* ew    = (const float*)d_in[2];
    const float* right = (const float*)d_in[3];
    const float* Wl1 = (const float*)d_in[5];
    const float* bl1 = (const float*)d_in[6];
    const float* Wl2 = (const float*)d_in[7];
    const float* bl2 = (const float*)d_in[8];
    const float* Wr1 = (const float*)d_in[9];
    const float* Wr2 = (const float*)d_in[10];
    const float* br2 = (const float*)d_in[11];
    const float* Wo1 = (const float*)d_in[12];
    const float* bo1 = (const float*)d_in[13];
    const float* Wo2 = (const float*)d_in[14];
    const float* bo2 = (const float*)d_in[15];

    const int nL = in_sizes[0] / 64;
    const int E  = in_sizes[1] / 2;
    const int nR = in_sizes[3] / 64;
    const int nO = out_size / EMB;

    float *gL, *gS, *gMl, *gMr, *gcl, *gcr;
    cudaGetSymbolAddress((void**)&gL,  g_L);
    cudaGetSymbolAddress((void**)&gS,  g_S);
    cudaGetSymbolAddress((void**)&gMl, g_Ml);
    cudaGetSymbolAddress((void**)&gMr, g_Mr);
    cudaGetSymbolAddress((void**)&gcl, g_cl);
    cudaGetSymbolAddress((void**)&gcr, g_cr);

    int *gCnt, *gRow, *gExcl, *gPart, *gPoff;
    int2* gEpack;
    cudaGetSymbolAddress((void**)&gCnt,   g_cnt);
    cudaGetSymbolAddress((void**)&gRow,   g_rowptr);
    cudaGetSymbolAddress((void**)&gExcl,  g_excl);
    cudaGetSymbolAddress((void**)&gPart,  g_part);
    cudaGetSymbolAddress((void**)&gPoff,  g_partoff);
    cudaGetSymbolAddress((void**)&gEpack, g_epack);

    __nv_bfloat16 *wl1t, *wr1t, *mlt, *mrt, *wo2t;
    cudaGetSymbolAddress((void**)&wl1t, g_Wl1T);
    cudaGetSymbolAddress((void**)&wr1t, g_Wr1T);
    cudaGetSymbolAddress((void**)&mlt,  g_MlT);
    cudaGetSymbolAddress((void**)&mrt,  g_MrT);
    cudaGetSymbolAddress((void**)&wo2t, g_Wo2T);

    cudaFuncSetAttribute(mlp_kernel,       cudaFuncAttributeMaxDynamicSharedMemorySize, MLP_SMEM_BYTES);
    cudaFuncSetAttribute(out_fused_kernel, cudaFuncAttributeMaxDynamicSharedMemorySize, F_SMEM_BYTES);

    // ---- weight prep ----
    fuse_weights_kernel<<<dim3(EMB, 2), EMB>>>(Wl2, Wr2, Wo1, gMl, gMr);
    fuse_bias_kernel<<<2, EMB>>>(bl2, br2, Wo1, gcl, gcr);
    prep_weights_kernel<<<5, EMB>>>(Wl1, Wr1, gMl, gMr, Wo2, wl1t, wr1t, mlt, mrt, wo2t);

    // ---- CSR build ----
    cudaMemsetAsync(gCnt, 0, (size_t)nR * sizeof(int));
    hist_kernel<<<(E + 255) / 256, 256>>>(eidx, gCnt, E);
    const int NB = (nR + 511) / 512;
    scan_block_kernel<<<NB, 512>>>(gCnt, gExcl, gPart, nR);
    scan_part_kernel<<<1, 1024>>>(gPart, gPoff, NB);
    finalize_rowptr_kernel<<<NB, 512>>>(gExcl, gPoff, gRow, gCnt, nR, E);
    fill_kernel<<<(E + 255) / 256, 256>>>(eidx, ew, gCnt, gEpack, E);

    const int gridL = (nL + 63) / 64;
    const int gridR = (nR + 63) / 64;
    const int gridO = (nO + 63) / 64;

    const uint4* wl1h = (const uint4*)wl1t;
    const uint4* wl1l = (const uint4*)(wl1t + EMB * 64);
    const uint4* wr1h = (const uint4*)wr1t;
    const uint4* wr1l = (const uint4*)(wr1t + EMB * 64);
    const uint4* mlh  = (const uint4*)mlt;
    const uint4* mll  = (const uint4*)(mlt + EMB * EMB);
    const uint4* mrh  = (const uint4*)mrt;
    const uint4* mrl  = (const uint4*)(mrt + EMB * EMB);
    const uint4* wo2h = (const uint4*)wo2t;
    const uint4* wo2l = (const uint4*)(wo2t + EMB * EMB);

    // L = relu(left@Wl1 + bl1) @ Ml + cl
    mlp_kernel<<<gridL, 256, MLP_SMEM_BYTES>>>(left, wl1h, wl1l, bl1, mlh, mll, gcl, gL, nL);
    // S = relu(right@Wr1) @ Mr + cr
    mlp_kernel<<<gridR, 256, MLP_SMEM_BYTES>>>(right, wr1h, wr1l, nullptr, mrh, mrl, gcr, gS, nR);
    // out = relu(S + gather + bo1) @ Wo2 + bo2  (fused)
    out_fused_kernel<<<gridO, 256, F_SMEM_BYTES>>>(gS, gRow, gEpack, gL,
                                                   wo2h, wo2l, bo1, bo2, (float*)d_out, nO);
}